// round 1
// baseline (speedup 1.0000x reference)
#include <cuda_runtime.h>

#define IMG_H 4096
#define IMG_W 4096
#define OT   64                 // output tile edge
#define HALO 7                  // max radius (k=15 -> p=7)
#define IT   (OT + 2*HALO)      // 78 input tile edge
#define SR   (IT + 1)           // 79 SAT rows/cols (zero border at row/col 0)
#define STRIDE 85               // gcd(85,32)=1 -> conflict-free row-prefix pass

__global__ __launch_bounds__(256) void meanconv_sat_kernel(
    const float* __restrict__ x,
    const float* __restrict__ mask,
    float* __restrict__ out)
{
    __shared__ float T[SR * STRIDE];   // 79*85*4 = 26.9 KB

    const int t   = threadIdx.x;
    const int gx0 = blockIdx.x * OT;
    const int gy0 = blockIdx.y * OT;

    // Zero SAT border (row 0 and col 0)
    for (int i = t; i < SR; i += 256) { T[i] = 0.0f; T[i * STRIDE] = 0.0f; }

    // Load 78x78 clamped input tile (clamping == replicate padding)
    for (int idx = t; idx < IT * IT; idx += 256) {
        int r = idx / IT;
        int c = idx - r * IT;
        int gy = gy0 - HALO + r; gy = gy < 0 ? 0 : (gy > IMG_H - 1 ? IMG_H - 1 : gy);
        int gx = gx0 - HALO + c; gx = gx < 0 ? 0 : (gx > IMG_W - 1 ? IMG_W - 1 : gx);
        T[(r + 1) * STRIDE + (c + 1)] = __ldg(&x[gy * IMG_W + gx]);
    }
    __syncthreads();

    // Column prefix sums (thread per column; FADD chain, loads independent)
    if (t < IT) {
        const int c = t + 1;
        float acc = 0.0f;
        #pragma unroll 6
        for (int r = 1; r < SR; r++) {
            acc += T[r * STRIDE + c];
            T[r * STRIDE + c] = acc;
        }
    }
    __syncthreads();

    // Row prefix sums (thread per row; stride 85 -> conflict-free across lanes)
    if (t < IT) {
        float* Trow = &T[(t + 1) * STRIDE];
        float acc = 0.0f;
        #pragma unroll 6
        for (int c = 1; c < SR; c++) {
            acc += Trow[c];
            Trow[c] = acc;
        }
    }
    __syncthreads();

    // Query: 4-corner SAT lookups per scale, 7 scales, 16 outputs/thread.
    // Lane -> consecutive x: conflict-free LDS, coalesced global I/O.
    const int tx = t & (OT - 1);
    const int ty = t >> 6;   // 0..3

    // w[p] = 1 / (7 * (2p+1)^2)
    const float w[8] = { 0.0f,
        1.0f/63.0f, 1.0f/175.0f, 1.0f/343.0f, 1.0f/567.0f,
        1.0f/847.0f, 1.0f/1183.0f, 1.0f/1575.0f };

    #pragma unroll 4
    for (int j = 0; j < 16; j++) {
        const int oy = ty * 16 + j;
        float acc = 0.0f;
        #pragma unroll
        for (int p = 1; p <= 7; p++) {
            const float* Tb = &T[(oy + 8 + p) * STRIDE];
            const float* Tt = &T[(oy + 7 - p) * STRIDE];
            const int cr = tx + 8 + p;
            const int cl = tx + 7 - p;
            acc += w[p] * (Tb[cr] - Tt[cr] - Tb[cl] + Tt[cl]);
        }
        const int g = (gy0 + oy) * IMG_W + (gx0 + tx);
        out[g] = acc * __ldg(&mask[g]);
    }
}

extern "C" void kernel_launch(void* const* d_in, const int* in_sizes, int n_in,
                              void* d_out, int out_size)
{
    const float* x    = (const float*)d_in[0];
    const float* mask = (const float*)d_in[1];
    float* out        = (float*)d_out;

    dim3 grid(IMG_W / OT, IMG_H / OT);   // 64 x 64 tiles
    meanconv_sat_kernel<<<grid, 256>>>(x, mask, out);
}